// round 1
// baseline (speedup 1.0000x reference)
#include <cuda_runtime.h>
#include <math.h>

#define DIM 32
#define NB 4096
#define KK 64
#define LL 2
#define N_ENTITY 500000
#define N_REL 64

// Scratch (allocation-free rule: __device__ globals)
__device__ float g_eproj[N_ENTITY * DIM];   // entity_emb @ W_ih[:, :32]^T
__device__ float g_rproj[N_REL * DIM];      // relation_emb @ W_ih[:, 32:]^T
__device__ float g_rrr[N_REL];              // dot(r, r)

// ---------------------------------------------------------------------------
// Kernel A: project all entity rows through the first half of W_ih.
// Eproj[i][d] = sum_e E[i][e] * W_ih[d*64 + e]
// ---------------------------------------------------------------------------
__global__ void project_entities(const float* __restrict__ E,
                                 const float* __restrict__ W_ih) {
    __shared__ float sW[32 * 32];  // sW[e*32 + d] = W_ih[d*64 + e]
    int tid = threadIdx.x;
    for (int i = tid; i < 1024; i += blockDim.x) {
        int d = i >> 5, e = i & 31;
        sW[e * 32 + d] = W_ih[d * 64 + e];
    }
    __syncthreads();
    int lane = tid & 31;
    int warp = tid >> 5;
    int warps_per_grid = (blockDim.x >> 5) * gridDim.x;
    int gw = blockIdx.x * (blockDim.x >> 5) + warp;
    for (int row = gw; row < N_ENTITY; row += warps_per_grid) {
        float ev = E[row * 32 + lane];
        float acc = 0.f;
        #pragma unroll
        for (int e = 0; e < 32; e++) {
            float be = __shfl_sync(0xffffffffu, ev, e);
            acc += be * sW[e * 32 + lane];
        }
        g_eproj[row * 32 + lane] = acc;
    }
}

// ---------------------------------------------------------------------------
// Kernel B: project the 64 relation rows through the second half of W_ih,
// and compute dot(r, r).
// ---------------------------------------------------------------------------
__global__ void project_relations(const float* __restrict__ R,
                                  const float* __restrict__ W_ih) {
    __shared__ float sW[32 * 32];  // sW[e*32 + d] = W_ih[d*64 + 32 + e]
    int tid = threadIdx.x;
    for (int i = tid; i < 1024; i += blockDim.x) {
        int d = i >> 5, e = i & 31;
        sW[e * 32 + d] = W_ih[d * 64 + 32 + e];
    }
    __syncthreads();
    int lane = tid & 31;
    int warp = tid >> 5;
    for (int rel = warp; rel < N_REL; rel += 8) {
        float rv = R[rel * 32 + lane];
        float acc = 0.f;
        float rr = rv * rv;
        #pragma unroll
        for (int e = 0; e < 32; e++) {
            acc += __shfl_sync(0xffffffffu, rv, e) * sW[e * 32 + lane];
        }
        #pragma unroll
        for (int off = 16; off; off >>= 1)
            rr += __shfl_xor_sync(0xffffffffu, rr, off);
        g_rproj[rel * 32 + lane] = acc;
        if (lane == 0) g_rrr[rel] = rr;
    }
}

// ---------------------------------------------------------------------------
// Main kernel: one block per user b (256 threads = 8 warps, warp per k).
// ---------------------------------------------------------------------------
__global__ __launch_bounds__(256)
void ripple_main(const int* __restrict__ users,
                 const int* __restrict__ items,
                 const int* __restrict__ hop0,
                 const int* __restrict__ heads,
                 const int* __restrict__ rels,
                 const int* __restrict__ tails,
                 const float* __restrict__ E,
                 const float* __restrict__ rec_user,
                 const float* __restrict__ rec_item,
                 const float* __restrict__ W_hh,
                 const float* __restrict__ b_ih,
                 const float* __restrict__ b_hh,
                 float* __restrict__ out) {
    __shared__ float sWhhT[32 * 32];   // sWhhT[d*32 + e] = W_hh[e*32 + d]
    __shared__ float sbias[32];
    __shared__ float slogit[KK];
    __shared__ float sh2[KK * DIM];
    __shared__ float sred[8 * DIM];
    __shared__ float s_stats[2];       // max, 1/sum

    int b = blockIdx.x;
    int tid = threadIdx.x;
    int lane = tid & 31;
    int warp = tid >> 5;

    for (int i = tid; i < 1024; i += 256) {
        int d = i >> 5, e = i & 31;
        sWhhT[d * 32 + e] = W_hh[e * 32 + d];
    }
    if (tid < 32) sbias[tid] = b_ih[tid] + b_hh[tid];
    __syncthreads();

    float oacc = 0.f;

    // hop-0 seed sum
    #pragma unroll
    for (int kk = 0; kk < 8; kk++) {
        int k = warp + kk * 8;
        int idx = hop0[b * KK + k];
        oacc += E[idx * 32 + lane];
    }

    for (int l = 0; l < LL; l++) {
        const int base = (l * NB + b) * KK;

        #pragma unroll
        for (int kk = 0; kk < 8; kk++) {
            int k = warp + kk * 8;
            int hidx = heads[base + k];
            int ridx = rels[base + k];
            int tidx = tails[base + k];

            float hx = E[hidx * 32 + lane];
            float tx = E[tidx * 32 + lane];
            float hp = g_eproj[hidx * 32 + lane];
            float tp = g_eproj[tidx * 32 + lane];
            float rp = g_rproj[ridx * 32 + lane];

            // logit = dot(h,t) + dot(r,r)
            float v = hx * tx;
            #pragma unroll
            for (int off = 16; off; off >>= 1)
                v += __shfl_xor_sync(0xffffffffu, v, off);
            if (lane == 0) slogit[k] = v + g_rrr[ridx];

            float bz = sbias[lane];
            float h1 = tanhf(hp + rp + bz);
            float acc = tp + rp + bz;
            #pragma unroll
            for (int d = 0; d < 32; d++) {
                float h1d = __shfl_sync(0xffffffffu, h1, d);
                acc += h1d * sWhhT[d * 32 + lane];
            }
            sh2[k * 32 + lane] = tanhf(acc);
        }
        __syncthreads();

        // softmax stats over the K=64 logits (warp 0)
        if (warp == 0) {
            float a = slogit[lane];
            float c = slogit[lane + 32];
            float m = fmaxf(a, c);
            #pragma unroll
            for (int off = 16; off; off >>= 1)
                m = fmaxf(m, __shfl_xor_sync(0xffffffffu, m, off));
            float s = expf(a - m) + expf(c - m);
            #pragma unroll
            for (int off = 16; off; off >>= 1)
                s += __shfl_xor_sync(0xffffffffu, s, off);
            if (lane == 0) { s_stats[0] = m; s_stats[1] = 1.f / s; }
        }
        __syncthreads();

        float m = s_stats[0];
        float inv = s_stats[1];
        #pragma unroll
        for (int kk = 0; kk < 8; kk++) {
            int k = warp + kk * 8;
            float pi = expf(slogit[k] - m) * inv;
            oacc += pi * sh2[k * 32 + lane];
        }
        __syncthreads();  // protect slogit/sh2 before next hop overwrites
    }

    sred[warp * 32 + lane] = oacc;
    __syncthreads();

    if (warp == 0) {
        float o = 0.f;
        #pragma unroll
        for (int w = 0; w < 8; w++) o += sred[w * 32 + lane];
        int u = users[b];
        int it = items[b];
        float uv = o + rec_user[u * 32 + lane];
        float iv = E[it * 32 + lane] + rec_item[it * 32 + lane];
        float v = uv * iv;
        #pragma unroll
        for (int off = 16; off; off >>= 1)
            v += __shfl_xor_sync(0xffffffffu, v, off);
        if (lane == 0) out[b] = 1.f / (1.f + expf(-v));
    }
}

// ---------------------------------------------------------------------------
extern "C" void kernel_launch(void* const* d_in, const int* in_sizes, int n_in,
                              void* d_out, int out_size) {
    const int*   users      = (const int*)d_in[0];
    const int*   items      = (const int*)d_in[1];
    const int*   hop0_items = (const int*)d_in[2];
    const int*   heads      = (const int*)d_in[3];
    const int*   relations  = (const int*)d_in[4];
    const int*   tails      = (const int*)d_in[5];
    const float* entity_emb = (const float*)d_in[6];
    const float* rel_emb    = (const float*)d_in[7];
    const float* rec_user   = (const float*)d_in[8];
    const float* rec_item   = (const float*)d_in[9];
    const float* W_ih       = (const float*)d_in[10];
    const float* W_hh       = (const float*)d_in[11];
    const float* b_ih       = (const float*)d_in[12];
    const float* b_hh       = (const float*)d_in[13];
    float* out = (float*)d_out;

    project_entities<<<1024, 256>>>(entity_emb, W_ih);
    project_relations<<<1, 256>>>(rel_emb, W_ih);
    ripple_main<<<NB, 256>>>(users, items, hop0_items, heads, relations, tails,
                             entity_emb, rec_user, rec_item,
                             W_hh, b_ih, b_hh, out);
}

// round 2
// speedup vs baseline: 1.1513x; 1.1513x over previous
#include <cuda_runtime.h>
#include <math.h>

#define DIM 32
#define NB 4096
#define KK 64
#define LL 2
#define N_ENTITY 500000
#define N_REL 64

// Scratch (allocation-free rule: __device__ globals)
__device__ float g_eproj[N_ENTITY * DIM];   // entity_emb @ W_ih[:, :32]^T
__device__ float g_rproj[N_REL * DIM];      // relation_emb @ W_ih[:, 32:]^T
__device__ float g_rrr[N_REL];              // dot(r, r)

__device__ __forceinline__ float tanh_approx(float x) {
    float y;
    asm("tanh.approx.f32 %0, %1;" : "=f"(y) : "f"(x));
    return y;
}

// ---------------------------------------------------------------------------
// Kernel A: project all entity rows through the first half of W_ih.
// Thread-per-row; row in registers; weights via warp-uniform LDS.128 broadcast.
// Eproj[i][d] = sum_e E[i][e] * W_ih[d*64 + e]
// ---------------------------------------------------------------------------
__global__ __launch_bounds__(256)
void project_entities(const float* __restrict__ E,
                      const float* __restrict__ W_ih) {
    __shared__ __align__(16) float sWT[32 * 32];  // sWT[e*32 + d] = W_ih[d*64 + e]
    int tid = threadIdx.x;
    for (int i = tid; i < 1024; i += 256) {
        int d = i >> 5, e = i & 31;
        sWT[e * 32 + d] = W_ih[d * 64 + e];
    }
    __syncthreads();

    int row = blockIdx.x * 256 + tid;
    if (row >= N_ENTITY) return;

    float4 x[8];
    const float4* rp = (const float4*)(E + row * 32);
    #pragma unroll
    for (int j = 0; j < 8; j++) x[j] = rp[j];

    float4 acc[8];
    #pragma unroll
    for (int j = 0; j < 8; j++) acc[j] = make_float4(0.f, 0.f, 0.f, 0.f);

    const float4* w4 = (const float4*)sWT;
    #pragma unroll
    for (int e = 0; e < 32; e++) {
        float xe = ((const float*)x)[e];   // e is compile-time after unroll
        #pragma unroll
        for (int j = 0; j < 8; j++) {
            float4 w = w4[e * 8 + j];      // warp-uniform address -> broadcast
            acc[j].x += xe * w.x;
            acc[j].y += xe * w.y;
            acc[j].z += xe * w.z;
            acc[j].w += xe * w.w;
        }
    }
    float4* op = (float4*)(g_eproj + row * 32);
    #pragma unroll
    for (int j = 0; j < 8; j++) op[j] = acc[j];
}

// ---------------------------------------------------------------------------
// Kernel B: project the 64 relation rows through the second half of W_ih,
// and compute dot(r, r). Tiny; unchanged.
// ---------------------------------------------------------------------------
__global__ void project_relations(const float* __restrict__ R,
                                  const float* __restrict__ W_ih) {
    __shared__ float sW[32 * 32];  // sW[e*32 + d] = W_ih[d*64 + 32 + e]
    int tid = threadIdx.x;
    for (int i = tid; i < 1024; i += blockDim.x) {
        int d = i >> 5, e = i & 31;
        sW[e * 32 + d] = W_ih[d * 64 + 32 + e];
    }
    __syncthreads();
    int lane = tid & 31;
    int warp = tid >> 5;
    for (int rel = warp; rel < N_REL; rel += 8) {
        float rv = R[rel * 32 + lane];
        float acc = 0.f;
        float rr = rv * rv;
        #pragma unroll
        for (int e = 0; e < 32; e++) {
            acc += __shfl_sync(0xffffffffu, rv, e) * sW[e * 32 + lane];
        }
        #pragma unroll
        for (int off = 16; off; off >>= 1)
            rr += __shfl_xor_sync(0xffffffffu, rr, off);
        g_rproj[rel * 32 + lane] = acc;
        if (lane == 0) g_rrr[rel] = rr;
    }
}

// ---------------------------------------------------------------------------
// Main kernel: one block per user b (256 threads = 8 warps, warp handles 8 k).
// Two passes per hop: pass 1 = logits (raw h,t gathers only), pass 2 = RNN
// (projection gathers only). W_hh row per lane in registers; h1 broadcast
// via 1 STS + 8 uniform LDS.128.
// ---------------------------------------------------------------------------
__global__ __launch_bounds__(256)
void ripple_main(const int* __restrict__ users,
                 const int* __restrict__ items,
                 const int* __restrict__ hop0,
                 const int* __restrict__ heads,
                 const int* __restrict__ rels,
                 const int* __restrict__ tails,
                 const float* __restrict__ E,
                 const float* __restrict__ rec_user,
                 const float* __restrict__ rec_item,
                 const float* __restrict__ W_hh,
                 const float* __restrict__ b_ih,
                 const float* __restrict__ b_hh,
                 float* __restrict__ out) {
    __shared__ float slogit[KK];
    __shared__ __align__(16) float sh1[8 * 32];
    __shared__ float sred[8 * 32];
    __shared__ float s_stats[2];       // max, 1/sum

    int b = blockIdx.x;
    int tid = threadIdx.x;
    int lane = tid & 31;
    int warp = tid >> 5;

    // per-lane register copy of W_hh row `lane` (h2[e] = sum_d h1[d]*W_hh[e][d])
    float4 whh[8];
    {
        const float4* wr = (const float4*)(W_hh + lane * 32);
        #pragma unroll
        for (int j = 0; j < 8; j++) whh[j] = wr[j];
    }
    float bz = b_ih[lane] + b_hh[lane];

    float oacc = 0.f;

    // hop-0 seed sum
    #pragma unroll
    for (int kk = 0; kk < 8; kk++) {
        int k = warp * 8 + kk;
        int idx = hop0[b * KK + k];
        oacc += E[idx * 32 + lane];
    }

    for (int l = 0; l < LL; l++) {
        const int base = (l * NB + b) * KK;

        // -------- pass 1: logits --------
        #pragma unroll
        for (int kk = 0; kk < 8; kk++) {
            int k = warp * 8 + kk;
            int hidx = heads[base + k];
            int ridx = rels[base + k];
            int tidx = tails[base + k];
            float v = E[hidx * 32 + lane] * E[tidx * 32 + lane];
            #pragma unroll
            for (int off = 16; off; off >>= 1)
                v += __shfl_xor_sync(0xffffffffu, v, off);
            if (lane == 0) slogit[k] = v + g_rrr[ridx];
        }
        __syncthreads();

        // softmax stats over the K=64 logits (warp 0)
        if (warp == 0) {
            float a = slogit[lane];
            float c = slogit[lane + 32];
            float m = fmaxf(a, c);
            #pragma unroll
            for (int off = 16; off; off >>= 1)
                m = fmaxf(m, __shfl_xor_sync(0xffffffffu, m, off));
            float s = __expf(a - m) + __expf(c - m);
            #pragma unroll
            for (int off = 16; off; off >>= 1)
                s += __shfl_xor_sync(0xffffffffu, s, off);
            if (lane == 0) { s_stats[0] = m; s_stats[1] = 1.f / s; }
        }
        __syncthreads();

        float m = s_stats[0];
        float inv = s_stats[1];

        // -------- pass 2: RNN + weighted accumulate --------
        #pragma unroll
        for (int kk = 0; kk < 8; kk++) {
            int k = warp * 8 + kk;
            int hidx = heads[base + k];
            int ridx = rels[base + k];
            int tidx = tails[base + k];

            float hp = g_eproj[hidx * 32 + lane];
            float tp = g_eproj[tidx * 32 + lane];
            float rp = g_rproj[ridx * 32 + lane];

            float h1 = tanh_approx(hp + rp + bz);
            sh1[warp * 32 + lane] = h1;
            __syncwarp();

            float acc = tp + rp + bz;
            const float4* hv4 = (const float4*)&sh1[warp * 32];
            #pragma unroll
            for (int j = 0; j < 8; j++) {
                float4 hv = hv4[j];        // warp-uniform -> broadcast
                acc += hv.x * whh[j].x;
                acc += hv.y * whh[j].y;
                acc += hv.z * whh[j].z;
                acc += hv.w * whh[j].w;
            }
            float h2 = tanh_approx(acc);
            float pi = __expf(slogit[k] - m) * inv;
            oacc += pi * h2;
            __syncwarp();   // protect sh1 before next kk overwrites
        }
        __syncthreads();    // protect slogit/s_stats before next hop
    }

    sred[warp * 32 + lane] = oacc;
    __syncthreads();

    if (warp == 0) {
        float o = 0.f;
        #pragma unroll
        for (int w = 0; w < 8; w++) o += sred[w * 32 + lane];
        int u = users[b];
        int it = items[b];
        float uv = o + rec_user[u * 32 + lane];
        float iv = E[it * 32 + lane] + rec_item[it * 32 + lane];
        float v = uv * iv;
        #pragma unroll
        for (int off = 16; off; off >>= 1)
            v += __shfl_xor_sync(0xffffffffu, v, off);
        if (lane == 0) out[b] = 1.f / (1.f + __expf(-v));
    }
}

// ---------------------------------------------------------------------------
extern "C" void kernel_launch(void* const* d_in, const int* in_sizes, int n_in,
                              void* d_out, int out_size) {
    const int*   users      = (const int*)d_in[0];
    const int*   items      = (const int*)d_in[1];
    const int*   hop0_items = (const int*)d_in[2];
    const int*   heads      = (const int*)d_in[3];
    const int*   relations  = (const int*)d_in[4];
    const int*   tails      = (const int*)d_in[5];
    const float* entity_emb = (const float*)d_in[6];
    const float* rel_emb    = (const float*)d_in[7];
    const float* rec_user   = (const float*)d_in[8];
    const float* rec_item   = (const float*)d_in[9];
    const float* W_ih       = (const float*)d_in[10];
    const float* W_hh       = (const float*)d_in[11];
    const float* b_ih       = (const float*)d_in[12];
    const float* b_hh       = (const float*)d_in[13];
    float* out = (float*)d_out;

    project_entities<<<(N_ENTITY + 255) / 256, 256>>>(entity_emb, W_ih);
    project_relations<<<1, 256>>>(rel_emb, W_ih);
    ripple_main<<<NB, 256>>>(users, items, hop0_items, heads, relations, tails,
                             entity_emb, rec_user, rec_item,
                             W_hh, b_ih, b_hh, out);
}

// round 3
// speedup vs baseline: 1.4394x; 1.2502x over previous
#include <cuda_runtime.h>
#include <math.h>

#define DIM 32
#define NB 4096
#define KK 64
#define LL 2
#define N_ENTITY 500000
#define N_REL 64

// Scratch (allocation-free rule: __device__ globals)
__device__ float g_eproj[N_ENTITY * DIM];   // entity_emb @ W_ih[:, :32]^T
__device__ float g_rproj[N_REL * DIM];      // relation_emb @ W_ih[:, 32:]^T
__device__ float g_rrr[N_REL];              // dot(r, r)

__device__ __forceinline__ float tanh_approx(float x) {
    float y;
    asm("tanh.approx.f32 %0, %1;" : "=f"(y) : "f"(x));
    return y;
}

// ---------------------------------------------------------------------------
// Kernel A: project all entity rows through the first half of W_ih.
// Thread-per-row; x streamed lazily (low regs -> higher occupancy);
// weights via warp-uniform LDS.128 broadcast.
// ---------------------------------------------------------------------------
__global__ __launch_bounds__(256, 4)
void project_entities(const float* __restrict__ E,
                      const float* __restrict__ W_ih) {
    __shared__ __align__(16) float sWT[32 * 32];  // sWT[e*32 + d] = W_ih[d*64 + e]
    int tid = threadIdx.x;
    for (int i = tid; i < 1024; i += 256) {
        int d = i >> 5, e = i & 31;
        sWT[e * 32 + d] = W_ih[d * 64 + e];
    }
    __syncthreads();

    int row = blockIdx.x * 256 + tid;
    if (row >= N_ENTITY) return;

    const float4* rp = (const float4*)(E + row * 32);
    const float4* w4 = (const float4*)sWT;

    float4 acc[8];
    #pragma unroll
    for (int j = 0; j < 8; j++) acc[j] = make_float4(0.f, 0.f, 0.f, 0.f);

    #pragma unroll
    for (int je = 0; je < 8; je++) {
        float4 x4 = rp[je];
        #pragma unroll
        for (int ee = 0; ee < 4; ee++) {
            float xe = (&x4.x)[ee];
            int e = je * 4 + ee;
            #pragma unroll
            for (int j = 0; j < 8; j++) {
                float4 w = w4[e * 8 + j];   // warp-uniform -> broadcast
                acc[j].x += xe * w.x;
                acc[j].y += xe * w.y;
                acc[j].z += xe * w.z;
                acc[j].w += xe * w.w;
            }
        }
    }
    float4* op = (float4*)(g_eproj + row * 32);
    #pragma unroll
    for (int j = 0; j < 8; j++) op[j] = acc[j];
}

// ---------------------------------------------------------------------------
// Kernel B: project the 64 relation rows through the second half of W_ih,
// and compute dot(r, r). Tiny.
// ---------------------------------------------------------------------------
__global__ void project_relations(const float* __restrict__ R,
                                  const float* __restrict__ W_ih) {
    __shared__ float sW[32 * 32];
    int tid = threadIdx.x;
    for (int i = tid; i < 1024; i += blockDim.x) {
        int d = i >> 5, e = i & 31;
        sW[e * 32 + d] = W_ih[d * 64 + 32 + e];
    }
    __syncthreads();
    int lane = tid & 31;
    int warp = tid >> 5;
    for (int rel = warp; rel < N_REL; rel += 8) {
        float rv = R[rel * 32 + lane];
        float acc = 0.f;
        float rr = rv * rv;
        #pragma unroll
        for (int e = 0; e < 32; e++) {
            acc += __shfl_sync(0xffffffffu, rv, e) * sW[e * 32 + lane];
        }
        #pragma unroll
        for (int off = 16; off; off >>= 1)
            rr += __shfl_xor_sync(0xffffffffu, rr, off);
        g_rproj[rel * 32 + lane] = acc;
        if (lane == 0) g_rrr[rel] = rr;
    }
}

// ---------------------------------------------------------------------------
// Main kernel: one block per user b (256 threads = 8 warps, warp handles 8 k,
// processed in independent PAIRS for memory-level parallelism).
// Single gather phase per hop: logit + h2 computed together; h2 -> smem;
// then softmax; then weighted sum.
// ---------------------------------------------------------------------------
__global__ __launch_bounds__(256)
void ripple_main(const int* __restrict__ users,
                 const int* __restrict__ items,
                 const int* __restrict__ hop0,
                 const int* __restrict__ heads,
                 const int* __restrict__ rels,
                 const int* __restrict__ tails,
                 const float* __restrict__ E,
                 const float* __restrict__ rec_user,
                 const float* __restrict__ rec_item,
                 const float* __restrict__ W_hh,
                 const float* __restrict__ b_ih,
                 const float* __restrict__ b_hh,
                 float* __restrict__ out) {
    __shared__ int s_hop0[KK];
    __shared__ int s_heads[LL * KK];
    __shared__ int s_rels[LL * KK];
    __shared__ int s_tails[LL * KK];
    __shared__ float slogit[KK];
    __shared__ __align__(16) float sh1[8 * 2 * 32];   // 2 slots per warp
    __shared__ float sh2[KK * DIM];
    __shared__ float sred[8 * 32];
    __shared__ float s_stats[2];

    int b = blockIdx.x;
    int tid = threadIdx.x;
    int lane = tid & 31;
    int warp = tid >> 5;

    // coalesced index preload
    if (tid < KK) s_hop0[tid] = hop0[b * KK + tid];
    for (int i = tid; i < LL * KK; i += 256) {
        int l = i >> 6, k = i & 63;
        int g = (l * NB + b) * KK + k;
        s_heads[i] = heads[g];
        s_rels[i]  = rels[g];
        s_tails[i] = tails[g];
    }

    // per-lane register copy of W_hh row `lane` (h2[e] += sum_d h1[d]*W_hh[e][d])
    float4 whh[8];
    {
        const float4* wr = (const float4*)(W_hh + lane * 32);
        #pragma unroll
        for (int j = 0; j < 8; j++) whh[j] = wr[j];
    }
    float bz = b_ih[lane] + b_hh[lane];
    __syncthreads();

    float oacc = 0.f;

    // hop-0 seed sum
    #pragma unroll
    for (int kk = 0; kk < 8; kk++) {
        int idx = s_hop0[warp * 8 + kk];
        oacc += E[idx * 32 + lane];
    }

    float* myh1a = &sh1[warp * 64];
    float* myh1b = &sh1[warp * 64 + 32];

    for (int l = 0; l < LL; l++) {
        const int sb = l * KK;

        #pragma unroll
        for (int p = 0; p < 4; p++) {
            int k0 = warp * 8 + p * 2;
            int k1 = k0 + 1;
            int h0 = s_heads[sb + k0], r0 = s_rels[sb + k0], t0 = s_tails[sb + k0];
            int h1i = s_heads[sb + k1], r1 = s_rels[sb + k1], t1 = s_tails[sb + k1];

            // issue all 10 gathers back-to-back
            float hx0 = E[h0 * 32 + lane];
            float tx0 = E[t0 * 32 + lane];
            float hx1 = E[h1i * 32 + lane];
            float tx1 = E[t1 * 32 + lane];
            float hp0 = g_eproj[h0 * 32 + lane];
            float tp0 = g_eproj[t0 * 32 + lane];
            float hp1 = g_eproj[h1i * 32 + lane];
            float tp1 = g_eproj[t1 * 32 + lane];
            float rp0 = g_rproj[r0 * 32 + lane];
            float rp1 = g_rproj[r1 * 32 + lane];

            // logits
            float v0 = hx0 * tx0;
            float v1 = hx1 * tx1;
            #pragma unroll
            for (int off = 16; off; off >>= 1) {
                v0 += __shfl_xor_sync(0xffffffffu, v0, off);
                v1 += __shfl_xor_sync(0xffffffffu, v1, off);
            }
            if (lane == 0) {
                slogit[k0] = v0 + g_rrr[r0];
                slogit[k1] = v1 + g_rrr[r1];
            }

            // RNN step
            float a0 = tanh_approx(hp0 + rp0 + bz);
            float a1 = tanh_approx(hp1 + rp1 + bz);
            myh1a[lane] = a0;
            myh1b[lane] = a1;
            __syncwarp();

            float acc0 = tp0 + rp0 + bz;
            float acc1 = tp1 + rp1 + bz;
            const float4* ha4 = (const float4*)myh1a;
            const float4* hb4 = (const float4*)myh1b;
            #pragma unroll
            for (int j = 0; j < 8; j++) {
                float4 ha = ha4[j];          // warp-uniform -> broadcast
                float4 hb = hb4[j];
                acc0 += ha.x * whh[j].x + ha.y * whh[j].y
                      + ha.z * whh[j].z + ha.w * whh[j].w;
                acc1 += hb.x * whh[j].x + hb.y * whh[j].y
                      + hb.z * whh[j].z + hb.w * whh[j].w;
            }
            sh2[k0 * 32 + lane] = tanh_approx(acc0);
            sh2[k1 * 32 + lane] = tanh_approx(acc1);
            __syncwarp();
        }
        __syncthreads();

        // softmax stats over the K=64 logits (warp 0)
        if (warp == 0) {
            float a = slogit[lane];
            float c = slogit[lane + 32];
            float m = fmaxf(a, c);
            #pragma unroll
            for (int off = 16; off; off >>= 1)
                m = fmaxf(m, __shfl_xor_sync(0xffffffffu, m, off));
            float s = __expf(a - m) + __expf(c - m);
            #pragma unroll
            for (int off = 16; off; off >>= 1)
                s += __shfl_xor_sync(0xffffffffu, s, off);
            if (lane == 0) { s_stats[0] = m; s_stats[1] = 1.f / s; }
        }
        __syncthreads();

        float m = s_stats[0];
        float inv = s_stats[1];
        #pragma unroll
        for (int kk = 0; kk < 8; kk++) {
            int k = warp * 8 + kk;
            float pi = __expf(slogit[k] - m) * inv;
            oacc += pi * sh2[k * 32 + lane];
        }
        __syncthreads();  // protect slogit/sh2/stats before next hop
    }

    sred[warp * 32 + lane] = oacc;
    __syncthreads();

    if (warp == 0) {
        float o = 0.f;
        #pragma unroll
        for (int w = 0; w < 8; w++) o += sred[w * 32 + lane];
        int u = users[b];
        int it = items[b];
        float uv = o + rec_user[u * 32 + lane];
        float iv = E[it * 32 + lane] + rec_item[it * 32 + lane];
        float v = uv * iv;
        #pragma unroll
        for (int off = 16; off; off >>= 1)
            v += __shfl_xor_sync(0xffffffffu, v, off);
        if (lane == 0) out[b] = 1.f / (1.f + __expf(-v));
    }
}

// ---------------------------------------------------------------------------
extern "C" void kernel_launch(void* const* d_in, const int* in_sizes, int n_in,
                              void* d_out, int out_size) {
    const int*   users      = (const int*)d_in[0];
    const int*   items      = (const int*)d_in[1];
    const int*   hop0_items = (const int*)d_in[2];
    const int*   heads      = (const int*)d_in[3];
    const int*   relations  = (const int*)d_in[4];
    const int*   tails      = (const int*)d_in[5];
    const float* entity_emb = (const float*)d_in[6];
    const float* rel_emb    = (const float*)d_in[7];
    const float* rec_user   = (const float*)d_in[8];
    const float* rec_item   = (const float*)d_in[9];
    const float* W_ih       = (const float*)d_in[10];
    const float* W_hh       = (const float*)d_in[11];
    const float* b_ih       = (const float*)d_in[12];
    const float* b_hh       = (const float*)d_in[13];
    float* out = (float*)d_out;

    project_entities<<<(N_ENTITY + 255) / 256, 256>>>(entity_emb, W_ih);
    project_relations<<<1, 256>>>(rel_emb, W_ih);
    ripple_main<<<NB, 256>>>(users, items, hop0_items, heads, relations, tails,
                             entity_emb, rec_user, rec_item,
                             W_hh, b_ih, b_hh, out);
}

// round 4
// speedup vs baseline: 1.4680x; 1.0199x over previous
#include <cuda_runtime.h>
#include <cuda_fp16.h>
#include <math.h>

#define DIM 32
#define NB 4096
#define KK 64
#define LL 2
#define N_ENTITY 500000
#define N_REL 64

// Scratch (allocation-free rule: __device__ globals)
// combo[i][d] = (half)E[i][d] in .x, (half)(E@W_ih_half1)[i][d] in .y
__device__ half2 g_combo[N_ENTITY * DIM];
__device__ float g_rproj[N_REL * DIM];      // relation_emb @ W_ih[:, 32:]^T
__device__ float g_rrr[N_REL];              // dot(r, r)

__device__ __forceinline__ float tanh_approx(float x) {
    float y;
    asm("tanh.approx.f32 %0, %1;" : "=f"(y) : "f"(x));
    return y;
}

// ---------------------------------------------------------------------------
// Kernel A: project all entity rows through the first half of W_ih and write
// the interleaved half2 combo table (raw E, Eproj).
// ---------------------------------------------------------------------------
__global__ __launch_bounds__(256, 4)
void project_entities(const float* __restrict__ E,
                      const float* __restrict__ W_ih) {
    __shared__ __align__(16) float sWT[32 * 32];  // sWT[e*32 + d] = W_ih[d*64 + e]
    int tid = threadIdx.x;
    for (int i = tid; i < 1024; i += 256) {
        int d = i >> 5, e = i & 31;
        sWT[e * 32 + d] = W_ih[d * 64 + e];
    }
    __syncthreads();

    int row = blockIdx.x * 256 + tid;
    if (row >= N_ENTITY) return;

    const float4* rp = (const float4*)(E + row * 32);
    const float4* w4 = (const float4*)sWT;

    float4 acc[8];
    #pragma unroll
    for (int j = 0; j < 8; j++) acc[j] = make_float4(0.f, 0.f, 0.f, 0.f);

    #pragma unroll
    for (int je = 0; je < 8; je++) {
        float4 x4 = rp[je];
        #pragma unroll
        for (int ee = 0; ee < 4; ee++) {
            float xe = (&x4.x)[ee];
            int e = je * 4 + ee;
            #pragma unroll
            for (int j = 0; j < 8; j++) {
                float4 w = w4[e * 8 + j];   // warp-uniform -> broadcast
                acc[j].x += xe * w.x;
                acc[j].y += xe * w.y;
                acc[j].z += xe * w.z;
                acc[j].w += xe * w.w;
            }
        }
    }

    uint4* cp = (uint4*)(g_combo + row * 32);
    #pragma unroll
    for (int j = 0; j < 8; j++) {
        float4 x4 = rp[j];                 // L1 hit reload
        half2 p0 = __floats2half2_rn(x4.x, acc[j].x);
        half2 p1 = __floats2half2_rn(x4.y, acc[j].y);
        half2 p2 = __floats2half2_rn(x4.z, acc[j].z);
        half2 p3 = __floats2half2_rn(x4.w, acc[j].w);
        uint4 o;
        o.x = *(unsigned int*)&p0;
        o.y = *(unsigned int*)&p1;
        o.z = *(unsigned int*)&p2;
        o.w = *(unsigned int*)&p3;
        cp[j] = o;
    }
}

// ---------------------------------------------------------------------------
// Kernel B: project the 64 relation rows through the second half of W_ih,
// and compute dot(r, r). Tiny.
// ---------------------------------------------------------------------------
__global__ void project_relations(const float* __restrict__ R,
                                  const float* __restrict__ W_ih) {
    __shared__ float sW[32 * 32];
    int tid = threadIdx.x;
    for (int i = tid; i < 1024; i += blockDim.x) {
        int d = i >> 5, e = i & 31;
        sW[e * 32 + d] = W_ih[d * 64 + 32 + e];
    }
    __syncthreads();
    int lane = tid & 31;
    int warp = tid >> 5;
    for (int rel = warp; rel < N_REL; rel += 8) {
        float rv = R[rel * 32 + lane];
        float acc = 0.f;
        float rr = rv * rv;
        #pragma unroll
        for (int e = 0; e < 32; e++) {
            acc += __shfl_sync(0xffffffffu, rv, e) * sW[e * 32 + lane];
        }
        #pragma unroll
        for (int off = 16; off; off >>= 1)
            rr += __shfl_xor_sync(0xffffffffu, rr, off);
        g_rproj[rel * 32 + lane] = acc;
        if (lane == 0) g_rrr[rel] = rr;
    }
}

// ---------------------------------------------------------------------------
// Main kernel: one block per user b (256 threads = 8 warps, warp handles 8 k).
// Per k: ONE half2 gather for head + ONE for tail (E and Eproj interleaved).
// rproj/rrr live in smem. 16 gathers per warp batched before compute.
// ---------------------------------------------------------------------------
__global__ __launch_bounds__(256)
void ripple_main(const int* __restrict__ users,
                 const int* __restrict__ items,
                 const int* __restrict__ hop0,
                 const int* __restrict__ heads,
                 const int* __restrict__ rels,
                 const int* __restrict__ tails,
                 const float* __restrict__ E,
                 const float* __restrict__ rec_user,
                 const float* __restrict__ rec_item,
                 const float* __restrict__ W_hh,
                 const float* __restrict__ b_ih,
                 const float* __restrict__ b_hh,
                 float* __restrict__ out) {
    __shared__ float s_rproj[N_REL * DIM];   // 8KB
    __shared__ float s_rrr[N_REL];
    __shared__ int s_hop0[KK];
    __shared__ int s_heads[LL * KK];
    __shared__ int s_rels[LL * KK];
    __shared__ int s_tails[LL * KK];
    __shared__ float slogit[KK];
    __shared__ __align__(16) float sh1[8 * 32];
    __shared__ float sh2[KK * DIM];
    __shared__ float sred[8 * 32];
    __shared__ float s_stats[2];

    int b = blockIdx.x;
    int tid = threadIdx.x;
    int lane = tid & 31;
    int warp = tid >> 5;

    // coalesced preloads
    if (tid < KK) s_hop0[tid] = hop0[b * KK + tid];
    if (tid < N_REL) s_rrr[tid] = g_rrr[tid];
    for (int i = tid; i < N_REL * DIM; i += 256) s_rproj[i] = g_rproj[i];
    for (int i = tid; i < LL * KK; i += 256) {
        int l = i >> 6, k = i & 63;
        int g = (l * NB + b) * KK + k;
        s_heads[i] = heads[g];
        s_rels[i]  = rels[g];
        s_tails[i] = tails[g];
    }

    // per-lane register copy of W_hh row `lane`
    float4 whh[8];
    {
        const float4* wr = (const float4*)(W_hh + lane * 32);
        #pragma unroll
        for (int j = 0; j < 8; j++) whh[j] = wr[j];
    }
    float bz = b_ih[lane] + b_hh[lane];
    __syncthreads();

    float oacc = 0.f;

    // hop-0 seed sum (E half from combo)
    {
        half2 hv[8];
        #pragma unroll
        for (int kk = 0; kk < 8; kk++) {
            int idx = s_hop0[warp * 8 + kk];
            hv[kk] = g_combo[idx * 32 + lane];
        }
        #pragma unroll
        for (int kk = 0; kk < 8; kk++) oacc += __low2float(hv[kk]);
    }

    float* myh1 = &sh1[warp * 32];

    for (int l = 0; l < LL; l++) {
        const int sb = l * KK;

        // batch all 16 gathers for this warp's 8 triples
        half2 hv[8], tv[8];
        int ridx[8];
        #pragma unroll
        for (int kk = 0; kk < 8; kk++) {
            int k = warp * 8 + kk;
            hv[kk] = g_combo[s_heads[sb + k] * 32 + lane];
            tv[kk] = g_combo[s_tails[sb + k] * 32 + lane];
            ridx[kk] = s_rels[sb + k];
        }

        #pragma unroll
        for (int kk = 0; kk < 8; kk++) {
            int k = warp * 8 + kk;
            float hE = __low2float(hv[kk]);
            float hP = __high2float(hv[kk]);
            float tE = __low2float(tv[kk]);
            float tP = __high2float(tv[kk]);
            float rp = s_rproj[ridx[kk] * 32 + lane];

            // logit = dot(h,t) + dot(r,r)
            float v = hE * tE;
            #pragma unroll
            for (int off = 16; off; off >>= 1)
                v += __shfl_xor_sync(0xffffffffu, v, off);
            if (lane == 0) slogit[k] = v + s_rrr[ridx[kk]];

            // RNN
            float h1 = tanh_approx(hP + rp + bz);
            myh1[lane] = h1;
            __syncwarp();
            float acc = tP + rp + bz;
            const float4* hv4 = (const float4*)myh1;
            #pragma unroll
            for (int j = 0; j < 8; j++) {
                float4 ha = hv4[j];          // warp-uniform -> broadcast
                acc += ha.x * whh[j].x + ha.y * whh[j].y
                     + ha.z * whh[j].z + ha.w * whh[j].w;
            }
            sh2[k * 32 + lane] = tanh_approx(acc);
            __syncwarp();
        }
        __syncthreads();

        // softmax stats over the K=64 logits (warp 0)
        if (warp == 0) {
            float a = slogit[lane];
            float c = slogit[lane + 32];
            float m = fmaxf(a, c);
            #pragma unroll
            for (int off = 16; off; off >>= 1)
                m = fmaxf(m, __shfl_xor_sync(0xffffffffu, m, off));
            float s = __expf(a - m) + __expf(c - m);
            #pragma unroll
            for (int off = 16; off; off >>= 1)
                s += __shfl_xor_sync(0xffffffffu, s, off);
            if (lane == 0) { s_stats[0] = m; s_stats[1] = 1.f / s; }
        }
        __syncthreads();

        float m = s_stats[0];
        float inv = s_stats[1];
        #pragma unroll
        for (int kk = 0; kk < 8; kk++) {
            int k = warp * 8 + kk;
            float pi = __expf(slogit[k] - m) * inv;
            oacc += pi * sh2[k * 32 + lane];
        }
        __syncthreads();  // protect slogit/sh2/stats before next hop
    }

    sred[warp * 32 + lane] = oacc;
    __syncthreads();

    if (warp == 0) {
        float o = 0.f;
        #pragma unroll
        for (int w = 0; w < 8; w++) o += sred[w * 32 + lane];
        int u = users[b];
        int it = items[b];
        float uv = o + rec_user[u * 32 + lane];
        float iv = E[it * 32 + lane] + rec_item[it * 32 + lane];   // fp32 path
        float v = uv * iv;
        #pragma unroll
        for (int off = 16; off; off >>= 1)
            v += __shfl_xor_sync(0xffffffffu, v, off);
        if (lane == 0) out[b] = 1.f / (1.f + __expf(-v));
    }
}

// ---------------------------------------------------------------------------
extern "C" void kernel_launch(void* const* d_in, const int* in_sizes, int n_in,
                              void* d_out, int out_size) {
    const int*   users      = (const int*)d_in[0];
    const int*   items      = (const int*)d_in[1];
    const int*   hop0_items = (const int*)d_in[2];
    const int*   heads      = (const int*)d_in[3];
    const int*   relations  = (const int*)d_in[4];
    const int*   tails      = (const int*)d_in[5];
    const float* entity_emb = (const float*)d_in[6];
    const float* rel_emb    = (const float*)d_in[7];
    const float* rec_user   = (const float*)d_in[8];
    const float* rec_item   = (const float*)d_in[9];
    const float* W_ih       = (const float*)d_in[10];
    const float* W_hh       = (const float*)d_in[11];
    const float* b_ih       = (const float*)d_in[12];
    const float* b_hh       = (const float*)d_in[13];
    float* out = (float*)d_out;

    project_entities<<<(N_ENTITY + 255) / 256, 256>>>(entity_emb, W_ih);
    project_relations<<<1, 256>>>(rel_emb, W_ih);
    ripple_main<<<NB, 256>>>(users, items, hop0_items, heads, relations, tails,
                             entity_emb, rec_user, rec_item,
                             W_hh, b_ih, b_hh, out);
}

// round 5
// speedup vs baseline: 1.5681x; 1.0681x over previous
#include <cuda_runtime.h>
#include <cuda_fp16.h>
#include <math.h>

#define DIM 32
#define NB 4096
#define KK 64
#define LL 2
#define N_ENTITY 500000
#define N_REL 64

// Scratch (allocation-free rule: __device__ globals)
// combo[i][d] = (half)E[i][d] in .x, (half)(E@W_ih_half1)[i][d] in .y
__device__ half2 g_combo[N_ENTITY * DIM];
__device__ float g_rproj[N_REL * DIM];      // relation_emb @ W_ih[:, 32:]^T
__device__ float g_rrr[N_REL];              // dot(r, r)

__device__ __forceinline__ float tanh_approx(float x) {
    float y;
    asm("tanh.approx.f32 %0, %1;" : "=f"(y) : "f"(x));
    return y;
}

// ---------------------------------------------------------------------------
// Kernel A: project entity rows through first half of W_ih, write combo table.
// TWO rows per thread: each LDS.128 weight load feeds 8 FMAs.
// ---------------------------------------------------------------------------
__global__ __launch_bounds__(256)
void project_entities(const float* __restrict__ E,
                      const float* __restrict__ W_ih) {
    __shared__ __align__(16) float sWT[32 * 32];  // sWT[e*32 + d] = W_ih[d*64 + e]
    int tid = threadIdx.x;
    for (int i = tid; i < 1024; i += 256) {
        int d = i >> 5, e = i & 31;
        sWT[e * 32 + d] = W_ih[d * 64 + e];
    }
    __syncthreads();

    int row0 = blockIdx.x * 512 + tid;
    int row1 = row0 + 256;
    if (row0 >= N_ENTITY) return;
    bool has1 = (row1 < N_ENTITY);

    const float4* rp0 = (const float4*)(E + row0 * 32);
    const float4* rp1 = (const float4*)(E + (has1 ? row1 : row0) * 32);
    const float4* w4 = (const float4*)sWT;

    float4 acc0[8], acc1[8];
    #pragma unroll
    for (int j = 0; j < 8; j++) {
        acc0[j] = make_float4(0.f, 0.f, 0.f, 0.f);
        acc1[j] = make_float4(0.f, 0.f, 0.f, 0.f);
    }

    #pragma unroll
    for (int je = 0; je < 8; je++) {
        float4 x0 = rp0[je];
        float4 x1 = rp1[je];
        #pragma unroll
        for (int ee = 0; ee < 4; ee++) {
            float a = (&x0.x)[ee];
            float c = (&x1.x)[ee];
            int e = je * 4 + ee;
            #pragma unroll
            for (int j = 0; j < 8; j++) {
                float4 w = w4[e * 8 + j];   // warp-uniform -> broadcast
                acc0[j].x += a * w.x;  acc1[j].x += c * w.x;
                acc0[j].y += a * w.y;  acc1[j].y += c * w.y;
                acc0[j].z += a * w.z;  acc1[j].z += c * w.z;
                acc0[j].w += a * w.w;  acc1[j].w += c * w.w;
            }
        }
    }

    uint4* cp0 = (uint4*)(g_combo + row0 * 32);
    #pragma unroll
    for (int j = 0; j < 8; j++) {
        float4 x4 = rp0[j];                 // L1 hit reload
        half2 p0 = __floats2half2_rn(x4.x, acc0[j].x);
        half2 p1 = __floats2half2_rn(x4.y, acc0[j].y);
        half2 p2 = __floats2half2_rn(x4.z, acc0[j].z);
        half2 p3 = __floats2half2_rn(x4.w, acc0[j].w);
        uint4 o;
        o.x = *(unsigned int*)&p0; o.y = *(unsigned int*)&p1;
        o.z = *(unsigned int*)&p2; o.w = *(unsigned int*)&p3;
        cp0[j] = o;
    }
    if (has1) {
        uint4* cp1 = (uint4*)(g_combo + row1 * 32);
        #pragma unroll
        for (int j = 0; j < 8; j++) {
            float4 x4 = rp1[j];
            half2 p0 = __floats2half2_rn(x4.x, acc1[j].x);
            half2 p1 = __floats2half2_rn(x4.y, acc1[j].y);
            half2 p2 = __floats2half2_rn(x4.z, acc1[j].z);
            half2 p3 = __floats2half2_rn(x4.w, acc1[j].w);
            uint4 o;
            o.x = *(unsigned int*)&p0; o.y = *(unsigned int*)&p1;
            o.z = *(unsigned int*)&p2; o.w = *(unsigned int*)&p3;
            cp1[j] = o;
        }
    }
}

// ---------------------------------------------------------------------------
// Kernel B: relation projections + dot(r,r). Tiny.
// ---------------------------------------------------------------------------
__global__ void project_relations(const float* __restrict__ R,
                                  const float* __restrict__ W_ih) {
    __shared__ float sW[32 * 32];
    int tid = threadIdx.x;
    for (int i = tid; i < 1024; i += blockDim.x) {
        int d = i >> 5, e = i & 31;
        sW[e * 32 + d] = W_ih[d * 64 + 32 + e];
    }
    __syncthreads();
    int lane = tid & 31;
    int warp = tid >> 5;
    for (int rel = warp; rel < N_REL; rel += 8) {
        float rv = R[rel * 32 + lane];
        float acc = 0.f;
        float rr = rv * rv;
        #pragma unroll
        for (int e = 0; e < 32; e++) {
            acc += __shfl_sync(0xffffffffu, rv, e) * sW[e * 32 + lane];
        }
        #pragma unroll
        for (int off = 16; off; off >>= 1)
            rr += __shfl_xor_sync(0xffffffffu, rr, off);
        g_rproj[rel * 32 + lane] = acc;
        if (lane == 0) g_rrr[rel] = rr;
    }
}

// ---------------------------------------------------------------------------
// Main kernel: one block per user (8 warps, warp = 8 k's).
// Phased per hop: batch gathers -> all h1 (1 syncwarp) -> interleaved logit
// reductions -> fully-pipelined joint matvec -> h2 in registers.
// ---------------------------------------------------------------------------
__global__ __launch_bounds__(256)
void ripple_main(const int* __restrict__ users,
                 const int* __restrict__ items,
                 const int* __restrict__ hop0,
                 const int* __restrict__ heads,
                 const int* __restrict__ rels,
                 const int* __restrict__ tails,
                 const float* __restrict__ E,
                 const float* __restrict__ rec_user,
                 const float* __restrict__ rec_item,
                 const float* __restrict__ W_hh,
                 const float* __restrict__ b_ih,
                 const float* __restrict__ b_hh,
                 float* __restrict__ out) {
    __shared__ float s_rproj[N_REL * DIM];      // 8KB
    __shared__ float s_rrr[N_REL];
    __shared__ int s_hop0[KK];
    __shared__ int s_heads[LL * KK];
    __shared__ int s_rels[LL * KK];
    __shared__ int s_tails[LL * KK];
    __shared__ float slogit[KK];
    __shared__ __align__(16) float sh1[8 * 8 * 32]; // 8KB: per-warp 8 h1 vectors
    __shared__ float sred[8 * 32];
    __shared__ float s_stats[2];

    int b = blockIdx.x;
    int tid = threadIdx.x;
    int lane = tid & 31;
    int warp = tid >> 5;

    // coalesced preloads
    if (tid < KK) s_hop0[tid] = hop0[b * KK + tid];
    if (tid < N_REL) s_rrr[tid] = g_rrr[tid];
    for (int i = tid; i < N_REL * DIM; i += 256) s_rproj[i] = g_rproj[i];
    for (int i = tid; i < LL * KK; i += 256) {
        int l = i >> 6, k = i & 63;
        int g = (l * NB + b) * KK + k;
        s_heads[i] = heads[g];
        s_rels[i]  = rels[g];
        s_tails[i] = tails[g];
    }

    // per-lane register copy of W_hh row `lane`
    float4 whh[8];
    {
        const float4* wr = (const float4*)(W_hh + lane * 32);
        #pragma unroll
        for (int j = 0; j < 8; j++) whh[j] = wr[j];
    }
    float bz = b_ih[lane] + b_hh[lane];
    __syncthreads();

    float oacc = 0.f;

    // hop-0 seed sum (E half from combo)
    {
        half2 hv[8];
        #pragma unroll
        for (int kk = 0; kk < 8; kk++) {
            int idx = s_hop0[warp * 8 + kk];
            hv[kk] = g_combo[idx * 32 + lane];
        }
        #pragma unroll
        for (int kk = 0; kk < 8; kk++) oacc += __low2float(hv[kk]);
    }

    float* myh1 = &sh1[warp * 256];

    for (int l = 0; l < LL; l++) {
        const int sb = l * KK;

        // phase a: batch all 16 gathers
        half2 hv[8], tv[8];
        int ridx[8];
        #pragma unroll
        for (int kk = 0; kk < 8; kk++) {
            int k = warp * 8 + kk;
            hv[kk] = g_combo[s_heads[sb + k] * 32 + lane];
            tv[kk] = g_combo[s_tails[sb + k] * 32 + lane];
            ridx[kk] = s_rels[sb + k];
        }

        // phase b: all 8 h1 -> smem, one syncwarp
        float rp[8];
        #pragma unroll
        for (int kk = 0; kk < 8; kk++)
            rp[kk] = s_rproj[ridx[kk] * 32 + lane];
        #pragma unroll
        for (int kk = 0; kk < 8; kk++)
            myh1[kk * 32 + lane] = tanh_approx(__high2float(hv[kk]) + rp[kk] + bz);

        // phase c: 8 interleaved independent logit reductions
        float v[8];
        #pragma unroll
        for (int kk = 0; kk < 8; kk++)
            v[kk] = __low2float(hv[kk]) * __low2float(tv[kk]);
        #pragma unroll
        for (int off = 16; off; off >>= 1) {
            #pragma unroll
            for (int kk = 0; kk < 8; kk++)
                v[kk] += __shfl_xor_sync(0xffffffffu, v[kk], off);
        }
        if (lane == 0) {
            #pragma unroll
            for (int kk = 0; kk < 8; kk++)
                slogit[warp * 8 + kk] = v[kk] + s_rrr[ridx[kk]];
        }
        __syncwarp();

        // phase d: joint matvec for all 8 k, j-outer (64 pipelined LDS.128)
        float acc[8];
        #pragma unroll
        for (int kk = 0; kk < 8; kk++)
            acc[kk] = __high2float(tv[kk]) + rp[kk] + bz;
        const float4* h1_4 = (const float4*)myh1;
        #pragma unroll
        for (int j = 0; j < 8; j++) {
            float4 wj = whh[j];
            #pragma unroll
            for (int kk = 0; kk < 8; kk++) {
                float4 ha = h1_4[kk * 8 + j];   // warp-uniform -> broadcast
                acc[kk] += ha.x * wj.x + ha.y * wj.y
                         + ha.z * wj.z + ha.w * wj.w;
            }
        }
        float h2[8];
        #pragma unroll
        for (int kk = 0; kk < 8; kk++) h2[kk] = tanh_approx(acc[kk]);
        __syncthreads();

        // softmax stats over the K=64 logits (warp 0)
        if (warp == 0) {
            float a = slogit[lane];
            float c = slogit[lane + 32];
            float m = fmaxf(a, c);
            #pragma unroll
            for (int off = 16; off; off >>= 1)
                m = fmaxf(m, __shfl_xor_sync(0xffffffffu, m, off));
            float s = __expf(a - m) + __expf(c - m);
            #pragma unroll
            for (int off = 16; off; off >>= 1)
                s += __shfl_xor_sync(0xffffffffu, s, off);
            if (lane == 0) { s_stats[0] = m; s_stats[1] = 1.f / s; }
        }
        __syncthreads();

        float m = s_stats[0];
        float inv = s_stats[1];
        #pragma unroll
        for (int kk = 0; kk < 8; kk++) {
            float pi = __expf(slogit[warp * 8 + kk] - m) * inv;
            oacc += pi * h2[kk];
        }
        __syncthreads();  // protect slogit/stats before next hop
    }

    sred[warp * 32 + lane] = oacc;
    __syncthreads();

    if (warp == 0) {
        float o = 0.f;
        #pragma unroll
        for (int w = 0; w < 8; w++) o += sred[w * 32 + lane];
        int u = users[b];
        int it = items[b];
        float uv = o + rec_user[u * 32 + lane];
        float iv = E[it * 32 + lane] + rec_item[it * 32 + lane];   // fp32 path
        float v = uv * iv;
        #pragma unroll
        for (int off = 16; off; off >>= 1)
            v += __shfl_xor_sync(0xffffffffu, v, off);
        if (lane == 0) out[b] = 1.f / (1.f + __expf(-v));
    }
}

// ---------------------------------------------------------------------------
extern "C" void kernel_launch(void* const* d_in, const int* in_sizes, int n_in,
                              void* d_out, int out_size) {
    const int*   users      = (const int*)d_in[0];
    const int*   items      = (const int*)d_in[1];
    const int*   hop0_items = (const int*)d_in[2];
    const int*   heads      = (const int*)d_in[3];
    const int*   relations  = (const int*)d_in[4];
    const int*   tails      = (const int*)d_in[5];
    const float* entity_emb = (const float*)d_in[6];
    const float* rel_emb    = (const float*)d_in[7];
    const float* rec_user   = (const float*)d_in[8];
    const float* rec_item   = (const float*)d_in[9];
    const float* W_ih       = (const float*)d_in[10];
    const float* W_hh       = (const float*)d_in[11];
    const float* b_ih       = (const float*)d_in[12];
    const float* b_hh       = (const float*)d_in[13];
    float* out = (float*)d_out;

    project_entities<<<(N_ENTITY + 511) / 512, 256>>>(entity_emb, W_ih);
    project_relations<<<1, 256>>>(rel_emb, W_ih);
    ripple_main<<<NB, 256>>>(users, items, hop0_items, heads, relations, tails,
                             entity_emb, rec_user, rec_item,
                             W_hh, b_ih, b_hh, out);
}